// round 1
// baseline (speedup 1.0000x reference)
#include <cuda_runtime.h>

#define BB    32
#define KK    1024
#define CC    256
#define PP    256
#define NSAMP 16
#define NROWS (BB*PP*NSAMP)   // 131072
#define NG    (BB*PP)         // 8192
#define HID   128
#define CIN0  259
#define OUTC  119

// output segment offsets (floats) in flattened tuple order:
// obj, center, hs, hrn, hr, ss, srn, sr, sem, new_xyz, inds
#define O_OBJ    0
#define O_CENTER 16384
#define O_HS     40960
#define O_HRN    139264
#define O_HR     237568
#define O_SS     335872
#define O_SRN    483328
#define O_SR     925696
#define O_SEM    1368064
#define O_NEWXYZ 1515520
#define O_INDS   1540096

// ---------------- scratch (device globals, no allocs) ----------------
__device__ int   g_inds[NG];
__device__ float g_newxyz[NG*3];
__device__ int   g_idx[NROWS];          // (b,p,s) flattened group indices
__device__ float g_x1[NROWS*HID];       // 64 MB, reused in-place for layers 1,2
__device__ float g_feat[NG*HID];        // 4 MB
__device__ float g_n1[NG*HID];          // 4 MB, reused in-place for FC2

__device__ __forceinline__ float* bufsel(int w) {
    if (w == 0) return g_x1;
    if (w == 1) return g_feat;
    return g_n1;
}

// ---------------- FPS: one block per batch, 1024 threads ----------------
__global__ void fps_kernel(const float* __restrict__ xyz) {
    __shared__ float sx[KK], sy[KK], sz[KK];
    __shared__ float swv[32];
    __shared__ int   swi[32];
    __shared__ int   s_last;

    const int b = blockIdx.x;
    const int t = threadIdx.x;
    const float* xb = xyz + (size_t)b * KK * 3;
    float x = xb[t*3+0], y = xb[t*3+1], z = xb[t*3+2];
    sx[t] = x; sy[t] = y; sz[t] = z;
    if (t == 0) {
        g_inds[b*PP] = 0;
        g_newxyz[(b*PP)*3+0] = x;
        g_newxyz[(b*PP)*3+1] = y;
        g_newxyz[(b*PP)*3+2] = z;
    }
    __syncthreads();

    float dist = 1e10f;
    int last = 0;
    for (int it = 1; it < PP; it++) {
        float lx = sx[last], ly = sy[last], lz = sz[last];
        float dx = x - lx, dy = y - ly, dz = z - lz;
        float d = fmaf(dz, dz, fmaf(dy, dy, dx*dx));
        dist = fminf(dist, d);

        // argmax with first-index tiebreak (matches jnp.argmax)
        float v = dist; int idx = t;
        #pragma unroll
        for (int o = 16; o > 0; o >>= 1) {
            float v2 = __shfl_down_sync(0xffffffffu, v, o);
            int   i2 = __shfl_down_sync(0xffffffffu, idx, o);
            if (v2 > v || (v2 == v && i2 < idx)) { v = v2; idx = i2; }
        }
        if ((t & 31) == 0) { swv[t>>5] = v; swi[t>>5] = idx; }
        __syncthreads();
        if (t < 32) {
            v = swv[t]; idx = swi[t];
            #pragma unroll
            for (int o = 16; o > 0; o >>= 1) {
                float v2 = __shfl_down_sync(0xffffffffu, v, o);
                int   i2 = __shfl_down_sync(0xffffffffu, idx, o);
                if (v2 > v || (v2 == v && i2 < idx)) { v = v2; idx = i2; }
            }
            if (t == 0) {
                s_last = idx;
                g_inds[b*PP + it] = idx;
                g_newxyz[(b*PP + it)*3+0] = sx[idx];
                g_newxyz[(b*PP + it)*3+1] = sy[idx];
                g_newxyz[(b*PP + it)*3+2] = sz[idx];
            }
        }
        __syncthreads();
        last = s_last;
    }
}

// ---------------- ball query: one block per batch, thread = one query ----------------
__global__ void ballquery_kernel(const float* __restrict__ xyz) {
    __shared__ float sx[KK], sy[KK], sz[KK];
    const int b = blockIdx.x;
    const int t = threadIdx.x;   // 256 threads = P queries
    const float* xb = xyz + (size_t)b * KK * 3;
    for (int i = t; i < KK; i += 256) {
        sx[i] = xb[i*3+0]; sy[i] = xb[i*3+1]; sz[i] = xb[i*3+2];
    }
    __syncthreads();

    const int gp = b*PP + t;
    float nx = g_newxyz[gp*3+0], ny = g_newxyz[gp*3+1], nz = g_newxyz[gp*3+2];
    int buf[NSAMP];
    int cnt = 0;
    for (int j = 0; j < KK; j++) {
        float dx = nx - sx[j], dy = ny - sy[j], dz = nz - sz[j];
        float d = fmaf(dz, dz, fmaf(dy, dy, dx*dx));
        if (d < 0.09f) {
            if (cnt < NSAMP) buf[cnt] = j;
            cnt++;
        }
    }
    if (cnt == 0) {
        #pragma unroll
        for (int s = 0; s < NSAMP; s++) buf[s] = KK - 1;
    } else {
        int c = cnt < NSAMP ? cnt : NSAMP;
        for (int s = c; s < NSAMP; s++) buf[s] = buf[0];
    }
    #pragma unroll
    for (int s = 0; s < NSAMP; s++) g_idx[gp*NSAMP + s] = buf[s];
}

// ---------------- layer0: gather-fused GEMM (131072x259)@(259x128) + relu ----------------
__global__ void layer0_kernel(const float* __restrict__ xyz,
                              const float* __restrict__ feats,
                              const float* __restrict__ W,
                              const float* __restrict__ bias,
                              const float* __restrict__ gam,
                              const float* __restrict__ bet) {
    __shared__ float As[16][128];
    __shared__ float Bs[16][128];
    __shared__ int   sj[128];
    __shared__ float sg3[128][3];

    const int t = threadIdx.x;
    const int tx = t & 15, ty = t >> 4;
    const int row0 = blockIdx.x * 128;
    const int lrow = t >> 1, lq = (t & 1) * 8;

    if (t < 128) {
        int grow = row0 + t;
        int b = grow >> 12;
        int rem = grow & 4095;
        int p = rem >> 4;
        int j = g_idx[grow];
        sj[t] = j;
        int gp = b*PP + p;
        #pragma unroll
        for (int d = 0; d < 3; d++)
            sg3[t][d] = __fdiv_rn(xyz[(size_t)(b*KK + j)*3 + d] - g_newxyz[gp*3 + d], 0.3f);
    }
    __syncthreads();

    float acc[8][8];
    #pragma unroll
    for (int i = 0; i < 8; i++)
        #pragma unroll
        for (int j = 0; j < 8; j++) acc[i][j] = 0.0f;

    const int bb = row0 >> 12;                  // block never spans batches (4096 % 128 == 0)
    const float* fb = feats + (size_t)bb * KK * CC;
    const float* frow = fb + (size_t)sj[lrow] * CC;

    for (int k0 = 0; k0 < 272; k0 += 16) {
        #pragma unroll
        for (int q = 0; q < 8; q++) {
            int k = k0 + lq + q;
            float v;
            if (k < 3)          v = sg3[lrow][k];
            else if (k < CIN0)  v = frow[k - 3];
            else                v = 0.0f;
            As[lq + q][lrow] = v;
        }
        int kk = k0 + ty;
        float4 b0, b1;
        if (kk < CIN0) {
            b0 = *(const float4*)(W + (size_t)kk*128 + tx*8);
            b1 = *(const float4*)(W + (size_t)kk*128 + tx*8 + 4);
        } else {
            b0 = make_float4(0.f,0.f,0.f,0.f);
            b1 = make_float4(0.f,0.f,0.f,0.f);
        }
        *(float4*)&Bs[ty][tx*8]     = b0;
        *(float4*)&Bs[ty][tx*8 + 4] = b1;
        __syncthreads();

        #pragma unroll
        for (int k = 0; k < 16; k++) {
            float a[8], bv[8];
            *(float4*)(a)   = *(const float4*)&As[k][ty*8];
            *(float4*)(a+4) = *(const float4*)&As[k][ty*8+4];
            *(float4*)(bv)   = *(const float4*)&Bs[k][tx*8];
            *(float4*)(bv+4) = *(const float4*)&Bs[k][tx*8+4];
            #pragma unroll
            for (int i = 0; i < 8; i++)
                #pragma unroll
                for (int j = 0; j < 8; j++)
                    acc[i][j] = fmaf(a[i], bv[j], acc[i][j]);
        }
        __syncthreads();
    }

    float gj[8], bj[8], ej[8];
    #pragma unroll
    for (int j = 0; j < 8; j++) {
        int c = tx*8 + j;
        gj[j] = gam[c]; bj[j] = bias[c]; ej[j] = bet[c];
    }
    #pragma unroll
    for (int i = 0; i < 8; i++) {
        int r = row0 + ty*8 + i;
        float vv[8];
        #pragma unroll
        for (int j = 0; j < 8; j++) {
            float v = fmaf(gj[j], acc[i][j] + bj[j], ej[j]);
            vv[j] = fmaxf(v, 0.0f);
        }
        *(float4*)(g_x1 + (size_t)r*128 + tx*8)     = make_float4(vv[0],vv[1],vv[2],vv[3]);
        *(float4*)(g_x1 + (size_t)r*128 + tx*8 + 4) = make_float4(vv[4],vv[5],vv[6],vv[7]);
    }
}

// ---------------- generic 128-K GEMM + affine + relu/relu6 ----------------
template<int ACT>   // 0: relu, 1: relu6
__global__ void gemm128_kernel(int abuf, const float* __restrict__ W,
                               const float* __restrict__ bias,
                               const float* __restrict__ gam,
                               const float* __restrict__ bet,
                               int ybuf) {
    const float* A = bufsel(abuf);
    float* Y = bufsel(ybuf);
    __shared__ float As[16][128];
    __shared__ float Bs[16][128];

    const int t = threadIdx.x;
    const int tx = t & 15, ty = t >> 4;
    const int row0 = blockIdx.x * 128;
    const int lrow = t >> 1, lq = (t & 1) * 8;

    float acc[8][8];
    #pragma unroll
    for (int i = 0; i < 8; i++)
        #pragma unroll
        for (int j = 0; j < 8; j++) acc[i][j] = 0.0f;

    for (int k0 = 0; k0 < 128; k0 += 16) {
        float4 a0 = *(const float4*)(A + (size_t)(row0+lrow)*128 + k0 + lq);
        float4 a1 = *(const float4*)(A + (size_t)(row0+lrow)*128 + k0 + lq + 4);
        As[lq+0][lrow] = a0.x; As[lq+1][lrow] = a0.y;
        As[lq+2][lrow] = a0.z; As[lq+3][lrow] = a0.w;
        As[lq+4][lrow] = a1.x; As[lq+5][lrow] = a1.y;
        As[lq+6][lrow] = a1.z; As[lq+7][lrow] = a1.w;
        *(float4*)&Bs[ty][tx*8]     = *(const float4*)(W + (size_t)(k0+ty)*128 + tx*8);
        *(float4*)&Bs[ty][tx*8 + 4] = *(const float4*)(W + (size_t)(k0+ty)*128 + tx*8 + 4);
        __syncthreads();

        #pragma unroll
        for (int k = 0; k < 16; k++) {
            float a[8], bv[8];
            *(float4*)(a)    = *(const float4*)&As[k][ty*8];
            *(float4*)(a+4)  = *(const float4*)&As[k][ty*8+4];
            *(float4*)(bv)   = *(const float4*)&Bs[k][tx*8];
            *(float4*)(bv+4) = *(const float4*)&Bs[k][tx*8+4];
            #pragma unroll
            for (int i = 0; i < 8; i++)
                #pragma unroll
                for (int j = 0; j < 8; j++)
                    acc[i][j] = fmaf(a[i], bv[j], acc[i][j]);
        }
        __syncthreads();
    }

    float gj[8], bj[8], ej[8];
    #pragma unroll
    for (int j = 0; j < 8; j++) {
        int c = tx*8 + j;
        gj[j] = gam[c]; bj[j] = bias[c]; ej[j] = bet[c];
    }
    #pragma unroll
    for (int i = 0; i < 8; i++) {
        int r = row0 + ty*8 + i;
        float vv[8];
        #pragma unroll
        for (int j = 0; j < 8; j++) {
            float v = fmaf(gj[j], acc[i][j] + bj[j], ej[j]);
            v = fmaxf(v, 0.0f);
            if (ACT == 1) v = fminf(v, 6.0f);
            vv[j] = v;
        }
        *(float4*)(Y + (size_t)r*128 + tx*8)     = make_float4(vv[0],vv[1],vv[2],vv[3]);
        *(float4*)(Y + (size_t)r*128 + tx*8 + 4) = make_float4(vv[4],vv[5],vv[6],vv[7]);
    }
}

// ---------------- maxpool over NS=16 samples ----------------
__global__ void maxpool_kernel() {
    int i = blockIdx.x * 256 + threadIdx.x;   // over NG*128
    int g = i >> 7, c = i & 127;
    const float* p = g_x1 + (size_t)(g*16)*128 + c;
    float m = p[0];
    #pragma unroll
    for (int s = 1; s < 16; s++) m = fmaxf(m, p[s*128]);
    g_feat[i] = m;
}

// ---------------- head: (8192x128)@(128x119) + b3, scattered outputs ----------------
__global__ void head_kernel(const float* __restrict__ W3,
                            const float* __restrict__ b3,
                            const float* __restrict__ msz,
                            float* __restrict__ out) {
    const float* A = g_n1;
    __shared__ float As[16][128];
    __shared__ float Bs[16][128];
    __shared__ float sb3[OUTC];
    __shared__ float sms[54];

    const int t = threadIdx.x;
    const int tx = t & 15, ty = t >> 4;
    const int row0 = blockIdx.x * 128;
    const int lrow = t >> 1, lq = (t & 1) * 8;

    if (t < OUTC) sb3[t] = b3[t];
    if (t >= 128 && t < 128 + 54) sms[t - 128] = msz[t - 128];

    float acc[8][8];
    #pragma unroll
    for (int i = 0; i < 8; i++)
        #pragma unroll
        for (int j = 0; j < 8; j++) acc[i][j] = 0.0f;

    for (int k0 = 0; k0 < 128; k0 += 16) {
        float4 a0 = *(const float4*)(A + (size_t)(row0+lrow)*128 + k0 + lq);
        float4 a1 = *(const float4*)(A + (size_t)(row0+lrow)*128 + k0 + lq + 4);
        As[lq+0][lrow] = a0.x; As[lq+1][lrow] = a0.y;
        As[lq+2][lrow] = a0.z; As[lq+3][lrow] = a0.w;
        As[lq+4][lrow] = a1.x; As[lq+5][lrow] = a1.y;
        As[lq+6][lrow] = a1.z; As[lq+7][lrow] = a1.w;
        int kk = k0 + ty;
        #pragma unroll
        for (int q = 0; q < 8; q++) {
            int c = tx*8 + q;
            Bs[ty][c] = (c < OUTC) ? W3[(size_t)kk*OUTC + c] : 0.0f;
        }
        __syncthreads();

        #pragma unroll
        for (int k = 0; k < 16; k++) {
            float a[8], bv[8];
            *(float4*)(a)    = *(const float4*)&As[k][ty*8];
            *(float4*)(a+4)  = *(const float4*)&As[k][ty*8+4];
            *(float4*)(bv)   = *(const float4*)&Bs[k][tx*8];
            *(float4*)(bv+4) = *(const float4*)&Bs[k][tx*8+4];
            #pragma unroll
            for (int i = 0; i < 8; i++)
                #pragma unroll
                for (int j = 0; j < 8; j++)
                    acc[i][j] = fmaf(a[i], bv[j], acc[i][j]);
        }
        __syncthreads();
    }

    const float HRS = (float)(3.14159265359 / 12.0);
    #pragma unroll
    for (int i = 0; i < 8; i++) {
        int r = row0 + ty*8 + i;
        #pragma unroll
        for (int j = 0; j < 8; j++) {
            int c = tx*8 + j;
            if (c >= OUTC) continue;
            float v = acc[i][j] + sb3[c];
            if (c < 3) {
                out[O_CENTER + r*3 + c] = g_newxyz[r*3 + c] + v;
            } else if (c < 5) {
                out[O_OBJ + r*2 + (c-3)] = v;
            } else if (c < 17) {
                out[O_HS + r*12 + (c-5)] = v;
            } else if (c < 35) {
                out[O_SS + r*18 + (c-17)] = v;
            } else if (c < 47) {
                out[O_HRN + r*12 + (c-35)] = v;
                out[O_HR  + r*12 + (c-35)] = v * HRS;
            } else if (c < 101) {
                int q = c - 47;
                out[O_SRN + r*54 + q] = v;
                out[O_SR  + r*54 + q] = v * sms[q];
            } else {
                out[O_SEM + r*18 + (c-101)] = v;
            }
        }
    }
}

// ---------------- tail: new_xyz + inds passthrough ----------------
__global__ void tail_kernel(float* __restrict__ out) {
    int i = blockIdx.x * 256 + threadIdx.x;
    if (i < NG*3) out[O_NEWXYZ + i] = g_newxyz[i];
    if (i < NG)   out[O_INDS + i] = (float)g_inds[i];
}

// ---------------- launch ----------------
extern "C" void kernel_launch(void* const* d_in, const int* in_sizes, int n_in,
                              void* d_out, int out_size) {
    const float* xyz      = (const float*)d_in[0];
    const float* features = (const float*)d_in[1];
    const float* msz      = (const float*)d_in[2];
    const float* w0  = (const float*)d_in[3];
    const float* b0  = (const float*)d_in[4];
    const float* gm0 = (const float*)d_in[5];
    const float* be0 = (const float*)d_in[6];
    const float* wm1 = (const float*)d_in[7];
    const float* bm1 = (const float*)d_in[8];
    const float* gm1 = (const float*)d_in[9];
    const float* bem1= (const float*)d_in[10];
    const float* wm2 = (const float*)d_in[11];
    const float* bm2 = (const float*)d_in[12];
    const float* gm2 = (const float*)d_in[13];
    const float* bem2= (const float*)d_in[14];
    const float* w1  = (const float*)d_in[15];
    const float* b1  = (const float*)d_in[16];
    const float* g1  = (const float*)d_in[17];
    const float* be1 = (const float*)d_in[18];
    const float* w2  = (const float*)d_in[19];
    const float* b2  = (const float*)d_in[20];
    const float* g2  = (const float*)d_in[21];
    const float* be2 = (const float*)d_in[22];
    const float* w3  = (const float*)d_in[23];
    const float* b3  = (const float*)d_in[24];
    float* out = (float*)d_out;

    fps_kernel<<<BB, 1024>>>(xyz);
    ballquery_kernel<<<BB, 256>>>(xyz);
    layer0_kernel<<<NROWS/128, 256>>>(xyz, features, w0, b0, gm0, be0);
    gemm128_kernel<0><<<NROWS/128, 256>>>(0, wm1, bm1, gm1, bem1, 0);
    gemm128_kernel<0><<<NROWS/128, 256>>>(0, wm2, bm2, gm2, bem2, 0);
    maxpool_kernel<<<(NG*HID)/256, 256>>>();
    gemm128_kernel<1><<<NG/128, 256>>>(1, w1, b1, g1, be1, 2);
    gemm128_kernel<1><<<NG/128, 256>>>(2, w2, b2, g2, be2, 2);
    head_kernel<<<NG/128, 256>>>(w3, b3, msz, out);
    tail_kernel<<<(NG*3 + 255)/256, 256>>>(out);
}

// round 3
// speedup vs baseline: 1.3646x; 1.3646x over previous
#include <cuda_runtime.h>
#include <cstdint>

#define BB    32
#define KK    1024
#define CC    256
#define PP    256
#define NSAMP 16
#define NROWS (BB*PP*NSAMP)   // 131072
#define NG    (BB*PP)         // 8192
#define HID   128
#define OUTC  119

// output segment offsets (floats): obj, center, hs, hrn, hr, ss, srn, sr, sem, new_xyz, inds
#define O_OBJ    0
#define O_CENTER 16384
#define O_HS     40960
#define O_HRN    139264
#define O_HR     237568
#define O_SS     335872
#define O_SRN    483328
#define O_SR     925696
#define O_SEM    1368064
#define O_NEWXYZ 1515520
#define O_INDS   1540096

// ---------------- scratch ----------------
__device__ int   g_inds[NG];
__device__ float g_newxyz[NG*3];
__device__ int   g_idx[NROWS];
__device__ float g_x1[NROWS*HID];    // row-major activations, reused in-place
__device__ float g_feat[NG*HID];
__device__ float g_n1[NG*HID];
// tf32-rounded weights, [k][n] row-major
__device__ float g_w0t[288*128];     // k<259 real, rest 0
__device__ float g_w1t[128*128];
__device__ float g_w2t[128*128];

__device__ __forceinline__ float* bufsel(int w) {
    if (w == 0) return g_x1;
    if (w == 1) return g_feat;
    return g_n1;
}

__device__ __forceinline__ float tf32r(float v) {
    float o;
    asm("cvt.rna.tf32.f32 %0, %1;" : "=f"(o) : "f"(v));
    return o;
}

// mma.sync m16n8k8 tf32: D += A*B, A row-frag (4 regs), B col-frag (2 regs)
__device__ __forceinline__ void mma8(float c[4], const float a[4], float b0, float b1) {
    asm volatile(
        "mma.sync.aligned.m16n8k8.row.col.f32.tf32.tf32.f32 "
        "{%0,%1,%2,%3}, {%4,%5,%6,%7}, {%8,%9}, {%0,%1,%2,%3};\n"
        : "+f"(c[0]), "+f"(c[1]), "+f"(c[2]), "+f"(c[3])
        : "r"(__float_as_uint(a[0])), "r"(__float_as_uint(a[1])),
          "r"(__float_as_uint(a[2])), "r"(__float_as_uint(a[3])),
          "r"(__float_as_uint(b0)), "r"(__float_as_uint(b1)));
}

// ---------------- FPS ----------------
__global__ void fps_kernel(const float* __restrict__ xyz) {
    __shared__ float sx[KK], sy[KK], sz[KK];
    __shared__ float swv[32];
    __shared__ int   swi[32];
    __shared__ int   s_last;
    const int b = blockIdx.x;
    const int t = threadIdx.x;
    const float* xb = xyz + (size_t)b * KK * 3;
    float x = xb[t*3+0], y = xb[t*3+1], z = xb[t*3+2];
    sx[t] = x; sy[t] = y; sz[t] = z;
    if (t == 0) {
        g_inds[b*PP] = 0;
        g_newxyz[(b*PP)*3+0] = x; g_newxyz[(b*PP)*3+1] = y; g_newxyz[(b*PP)*3+2] = z;
    }
    __syncthreads();
    float dist = 1e10f;
    int last = 0;
    for (int it = 1; it < PP; it++) {
        float dx = x - sx[last], dy = y - sy[last], dz = z - sz[last];
        float d = fmaf(dz, dz, fmaf(dy, dy, dx*dx));
        dist = fminf(dist, d);
        float v = dist; int idx = t;
        #pragma unroll
        for (int o = 16; o > 0; o >>= 1) {
            float v2 = __shfl_down_sync(0xffffffffu, v, o);
            int   i2 = __shfl_down_sync(0xffffffffu, idx, o);
            if (v2 > v || (v2 == v && i2 < idx)) { v = v2; idx = i2; }
        }
        if ((t & 31) == 0) { swv[t>>5] = v; swi[t>>5] = idx; }
        __syncthreads();
        if (t < 32) {
            v = swv[t]; idx = swi[t];
            #pragma unroll
            for (int o = 16; o > 0; o >>= 1) {
                float v2 = __shfl_down_sync(0xffffffffu, v, o);
                int   i2 = __shfl_down_sync(0xffffffffu, idx, o);
                if (v2 > v || (v2 == v && i2 < idx)) { v = v2; idx = i2; }
            }
            if (t == 0) {
                s_last = idx;
                g_inds[b*PP + it] = idx;
                g_newxyz[(b*PP + it)*3+0] = sx[idx];
                g_newxyz[(b*PP + it)*3+1] = sy[idx];
                g_newxyz[(b*PP + it)*3+2] = sz[idx];
            }
        }
        __syncthreads();
        last = s_last;
    }
}

// ---------------- ball query ----------------
__global__ void ballquery_kernel(const float* __restrict__ xyz) {
    __shared__ float sx[KK], sy[KK], sz[KK];
    const int b = blockIdx.x;
    const int t = threadIdx.x;
    const float* xb = xyz + (size_t)b * KK * 3;
    for (int i = t; i < KK; i += 256) { sx[i] = xb[i*3+0]; sy[i] = xb[i*3+1]; sz[i] = xb[i*3+2]; }
    __syncthreads();
    const int gp = b*PP + t;
    float nx = g_newxyz[gp*3+0], ny = g_newxyz[gp*3+1], nz = g_newxyz[gp*3+2];
    int buf[NSAMP]; int cnt = 0;
    for (int j = 0; j < KK; j++) {
        float dx = nx - sx[j], dy = ny - sy[j], dz = nz - sz[j];
        float d = fmaf(dz, dz, fmaf(dy, dy, dx*dx));
        if (d < 0.09f) { if (cnt < NSAMP) buf[cnt] = j; cnt++; }
    }
    if (cnt == 0) { for (int s = 0; s < NSAMP; s++) buf[s] = KK - 1; }
    else { int c = cnt < NSAMP ? cnt : NSAMP; for (int s = c; s < NSAMP; s++) buf[s] = buf[0]; }
    #pragma unroll
    for (int s = 0; s < NSAMP; s++) g_idx[gp*NSAMP + s] = buf[s];
}

// ---------------- weight prep (tf32 round, pad K for layer0) ----------------
__global__ void prep_w0(const float* __restrict__ w) {   // w: [259][128] -> g_w0t [288][128]
    int i = blockIdx.x * 256 + threadIdx.x;
    if (i >= 288*128) return;
    int k = i >> 7;
    g_w0t[i] = (k < 259) ? tf32r(w[i]) : 0.0f;
}
__global__ void prep_w128(const float* __restrict__ w, int which) {  // [128][128]
    int i = blockIdx.x * 256 + threadIdx.x;
    float* dst = (which == 1) ? g_w1t : g_w2t;
    dst[i] = tf32r(w[i]);
}

// ---------------- tf32 mma GEMM, layers 1&2: g_x1 (in-place), K=128 ----------------
__global__ void mma_gemm_kernel(int which,
                                const float* __restrict__ bias,
                                const float* __restrict__ gam,
                                const float* __restrict__ bet) {
    __shared__ float As[128][36];    // [row][k], pad 36 -> bank = 4*row + k (conflict-free frags)
    __shared__ float Bs[32][136];    // [k][n],  pad 136 -> bank = 8*k + n
    __shared__ float sg[128], sb[128], se[128];

    const float* Wt = (which == 1) ? g_w1t : g_w2t;
    float* A_ = g_x1;
    const int tid = threadIdx.x;
    const int row0 = blockIdx.x * 128;
    const int lane = tid & 31, wid = tid >> 5;
    const int warp_m = wid >> 1, warp_n = wid & 1;
    const int grp = lane >> 2, tig = lane & 3;
    if (tid < 128) { sg[tid] = gam[tid]; sb[tid] = bias[tid]; se[tid] = bet[tid]; }

    float acc[2][8][4];
    #pragma unroll
    for (int mt = 0; mt < 2; mt++)
        #pragma unroll
        for (int nt = 0; nt < 8; nt++)
            #pragma unroll
            for (int q = 0; q < 4; q++) acc[mt][nt][q] = 0.0f;

    const int ar = tid >> 1, ah = (tid & 1) * 16;
    const int bk = tid >> 3, bc = (tid & 7) * 16;

    for (int kc = 0; kc < 128; kc += 32) {
        const float* ap = A_ + (size_t)(row0 + ar) * 128 + kc + ah;
        #pragma unroll
        for (int q = 0; q < 16; q += 4) {
            float4 v = *(const float4*)(ap + q);
            v.x = tf32r(v.x); v.y = tf32r(v.y); v.z = tf32r(v.z); v.w = tf32r(v.w);
            *(float4*)&As[ar][ah + q] = v;
        }
        const float* bp = Wt + (size_t)(kc + bk) * 128 + bc;
        #pragma unroll
        for (int q = 0; q < 16; q += 4)
            *(float4*)&Bs[bk][bc + q] = *(const float4*)(bp + q);
        __syncthreads();

        #pragma unroll
        for (int ks = 0; ks < 32; ks += 8) {
            float a[2][4];
            #pragma unroll
            for (int mt = 0; mt < 2; mt++) {
                int r0 = warp_m*32 + mt*16 + grp;
                a[mt][0] = As[r0][ks + tig];
                a[mt][1] = As[r0 + 8][ks + tig];
                a[mt][2] = As[r0][ks + tig + 4];
                a[mt][3] = As[r0 + 8][ks + tig + 4];
            }
            #pragma unroll
            for (int nt = 0; nt < 8; nt++) {
                int c0 = warp_n*64 + nt*8 + grp;
                float b0 = Bs[ks + tig][c0];
                float b1 = Bs[ks + tig + 4][c0];
                mma8(acc[0][nt], a[0], b0, b1);
                mma8(acc[1][nt], a[1], b0, b1);
            }
        }
        __syncthreads();
    }

    #pragma unroll
    for (int mt = 0; mt < 2; mt++) {
        int rbase = row0 + warp_m*32 + mt*16 + grp;
        #pragma unroll
        for (int nt = 0; nt < 8; nt++) {
            int c = warp_n*64 + nt*8 + tig*2;
            float g0 = sg[c], g1 = sg[c+1], bb0 = sb[c], bb1 = sb[c+1], e0 = se[c], e1 = se[c+1];
            float v0 = fmaxf(fmaf(g0, acc[mt][nt][0] + bb0, e0), 0.0f);
            float v1 = fmaxf(fmaf(g1, acc[mt][nt][1] + bb1, e1), 0.0f);
            float v2 = fmaxf(fmaf(g0, acc[mt][nt][2] + bb0, e0), 0.0f);
            float v3 = fmaxf(fmaf(g1, acc[mt][nt][3] + bb1, e1), 0.0f);
            *(float2*)&A_[(size_t)rbase*128 + c]     = make_float2(v0, v1);
            *(float2*)&A_[(size_t)(rbase+8)*128 + c] = make_float2(v2, v3);
        }
    }
}

// ---------------- tf32 mma GEMM, layer 0: gathered A, K=288 ----------------
__global__ void mma_layer0_kernel(const float* __restrict__ xyz,
                                  const float* __restrict__ feats,
                                  const float* __restrict__ bias,
                                  const float* __restrict__ gam,
                                  const float* __restrict__ bet) {
    __shared__ float As[128][36];
    __shared__ float Bs[32][136];
    __shared__ float sg[128], sb[128], se[128];
    __shared__ int   sj[128];
    __shared__ float sg3[128][3];

    const int tid = threadIdx.x;
    const int row0 = blockIdx.x * 128;
    const int lane = tid & 31, wid = tid >> 5;
    const int warp_m = wid >> 1, warp_n = wid & 1;
    const int grp = lane >> 2, tig = lane & 3;

    if (tid < 128) { sg[tid] = gam[tid]; sb[tid] = bias[tid]; se[tid] = bet[tid]; }
    if (tid < 128) {
        int grow = row0 + tid;
        int b = grow >> 12;
        int p = (grow & 4095) >> 4;
        int j = g_idx[grow];
        sj[tid] = j;
        int gp = b * PP + p;
        #pragma unroll
        for (int d = 0; d < 3; d++)
            sg3[tid][d] = __fdiv_rn(xyz[(size_t)(b*KK + j)*3 + d] - g_newxyz[gp*3 + d], 0.3f);
    }
    __syncthreads();

    float acc[2][8][4];
    #pragma unroll
    for (int mt = 0; mt < 2; mt++)
        #pragma unroll
        for (int nt = 0; nt < 8; nt++)
            #pragma unroll
            for (int q = 0; q < 4; q++) acc[mt][nt][q] = 0.0f;

    const int ar = tid >> 1, ah = (tid & 1) * 16;
    const int bk = tid >> 3, bc = (tid & 7) * 16;
    const int bbatch = row0 >> 12;
    const float* frow = feats + (size_t)(bbatch * KK + sj[ar]) * CC;

    for (int kc = 0; kc < 288; kc += 32) {
        #pragma unroll
        for (int q = 0; q < 16; q++) {
            int k = kc + ah + q;
            float v;
            if (k < 3)        v = sg3[ar][k];
            else if (k < 259) v = __ldg(frow + k - 3);
            else              v = 0.0f;
            As[ar][ah + q] = tf32r(v);
        }
        const float* bp = g_w0t + (size_t)(kc + bk) * 128 + bc;
        #pragma unroll
        for (int q = 0; q < 16; q += 4)
            *(float4*)&Bs[bk][bc + q] = *(const float4*)(bp + q);
        __syncthreads();

        #pragma unroll
        for (int ks = 0; ks < 32; ks += 8) {
            float a[2][4];
            #pragma unroll
            for (int mt = 0; mt < 2; mt++) {
                int r0 = warp_m*32 + mt*16 + grp;
                a[mt][0] = As[r0][ks + tig];
                a[mt][1] = As[r0 + 8][ks + tig];
                a[mt][2] = As[r0][ks + tig + 4];
                a[mt][3] = As[r0 + 8][ks + tig + 4];
            }
            #pragma unroll
            for (int nt = 0; nt < 8; nt++) {
                int c0 = warp_n*64 + nt*8 + grp;
                float b0 = Bs[ks + tig][c0];
                float b1 = Bs[ks + tig + 4][c0];
                mma8(acc[0][nt], a[0], b0, b1);
                mma8(acc[1][nt], a[1], b0, b1);
            }
        }
        __syncthreads();
    }

    #pragma unroll
    for (int mt = 0; mt < 2; mt++) {
        int rbase = row0 + warp_m*32 + mt*16 + grp;
        #pragma unroll
        for (int nt = 0; nt < 8; nt++) {
            int c = warp_n*64 + nt*8 + tig*2;
            float g0 = sg[c], g1 = sg[c+1], bb0 = sb[c], bb1 = sb[c+1], e0 = se[c], e1 = se[c+1];
            float v0 = fmaxf(fmaf(g0, acc[mt][nt][0] + bb0, e0), 0.0f);
            float v1 = fmaxf(fmaf(g1, acc[mt][nt][1] + bb1, e1), 0.0f);
            float v2 = fmaxf(fmaf(g0, acc[mt][nt][2] + bb0, e0), 0.0f);
            float v3 = fmaxf(fmaf(g1, acc[mt][nt][3] + bb1, e1), 0.0f);
            *(float2*)&g_x1[(size_t)rbase*128 + c]     = make_float2(v0, v1);
            *(float2*)&g_x1[(size_t)(rbase+8)*128 + c] = make_float2(v2, v3);
        }
    }
}

// ---------------- maxpool over NS=16 samples (row-major) ----------------
__global__ void maxpool_kernel() {
    int i = blockIdx.x * 256 + threadIdx.x;   // over NG*128
    int g = i >> 7, c = i & 127;
    const float* p = g_x1 + (size_t)(g*16)*128 + c;
    float m = p[0];
    #pragma unroll
    for (int s = 1; s < 16; s++) m = fmaxf(m, p[s*128]);
    g_feat[i] = m;
}

// ---------------- fp32 SGEMM for FC layers (rows=8192, K=128) ----------------
template<int ACT>
__global__ void gemm128_kernel(int abuf, const float* __restrict__ W,
                               const float* __restrict__ bias,
                               const float* __restrict__ gam,
                               const float* __restrict__ bet,
                               int ybuf) {
    const float* A = bufsel(abuf);
    float* Y = bufsel(ybuf);
    __shared__ float As[16][128];
    __shared__ float Bs[16][128];
    const int t = threadIdx.x;
    const int tx = t & 15, ty = t >> 4;
    const int row0 = blockIdx.x * 128;
    const int lrow = t >> 1, lq = (t & 1) * 8;
    float acc[8][8];
    #pragma unroll
    for (int i = 0; i < 8; i++)
        #pragma unroll
        for (int j = 0; j < 8; j++) acc[i][j] = 0.0f;
    for (int k0 = 0; k0 < 128; k0 += 16) {
        float4 a0 = *(const float4*)(A + (size_t)(row0+lrow)*128 + k0 + lq);
        float4 a1 = *(const float4*)(A + (size_t)(row0+lrow)*128 + k0 + lq + 4);
        As[lq+0][lrow] = a0.x; As[lq+1][lrow] = a0.y; As[lq+2][lrow] = a0.z; As[lq+3][lrow] = a0.w;
        As[lq+4][lrow] = a1.x; As[lq+5][lrow] = a1.y; As[lq+6][lrow] = a1.z; As[lq+7][lrow] = a1.w;
        *(float4*)&Bs[ty][tx*8]     = *(const float4*)(W + (size_t)(k0+ty)*128 + tx*8);
        *(float4*)&Bs[ty][tx*8 + 4] = *(const float4*)(W + (size_t)(k0+ty)*128 + tx*8 + 4);
        __syncthreads();
        #pragma unroll
        for (int k = 0; k < 16; k++) {
            float a[8], bv[8];
            *(float4*)(a)    = *(const float4*)&As[k][ty*8];
            *(float4*)(a+4)  = *(const float4*)&As[k][ty*8+4];
            *(float4*)(bv)   = *(const float4*)&Bs[k][tx*8];
            *(float4*)(bv+4) = *(const float4*)&Bs[k][tx*8+4];
            #pragma unroll
            for (int i = 0; i < 8; i++)
                #pragma unroll
                for (int j = 0; j < 8; j++)
                    acc[i][j] = fmaf(a[i], bv[j], acc[i][j]);
        }
        __syncthreads();
    }
    float gj[8], bj[8], ej[8];
    #pragma unroll
    for (int j = 0; j < 8; j++) { int c = tx*8 + j; gj[j] = gam[c]; bj[j] = bias[c]; ej[j] = bet[c]; }
    #pragma unroll
    for (int i = 0; i < 8; i++) {
        int r = row0 + ty*8 + i;
        float vv[8];
        #pragma unroll
        for (int j = 0; j < 8; j++) {
            float v = fmaf(gj[j], acc[i][j] + bj[j], ej[j]);
            v = fmaxf(v, 0.0f);
            if (ACT == 1) v = fminf(v, 6.0f);
            vv[j] = v;
        }
        *(float4*)(Y + (size_t)r*128 + tx*8)     = make_float4(vv[0],vv[1],vv[2],vv[3]);
        *(float4*)(Y + (size_t)r*128 + tx*8 + 4) = make_float4(vv[4],vv[5],vv[6],vv[7]);
    }
}

// ---------------- head ----------------
__global__ void head_kernel(const float* __restrict__ W3,
                            const float* __restrict__ b3,
                            const float* __restrict__ msz,
                            float* __restrict__ out) {
    const float* A = g_n1;
    __shared__ float As[16][128];
    __shared__ float Bs[16][128];
    __shared__ float sb3[OUTC];
    __shared__ float sms[54];
    const int t = threadIdx.x;
    const int tx = t & 15, ty = t >> 4;
    const int row0 = blockIdx.x * 128;
    const int lrow = t >> 1, lq = (t & 1) * 8;
    if (t < OUTC) sb3[t] = b3[t];
    if (t >= 128 && t < 128 + 54) sms[t - 128] = msz[t - 128];
    float acc[8][8];
    #pragma unroll
    for (int i = 0; i < 8; i++)
        #pragma unroll
        for (int j = 0; j < 8; j++) acc[i][j] = 0.0f;
    for (int k0 = 0; k0 < 128; k0 += 16) {
        float4 a0 = *(const float4*)(A + (size_t)(row0+lrow)*128 + k0 + lq);
        float4 a1 = *(const float4*)(A + (size_t)(row0+lrow)*128 + k0 + lq + 4);
        As[lq+0][lrow] = a0.x; As[lq+1][lrow] = a0.y; As[lq+2][lrow] = a0.z; As[lq+3][lrow] = a0.w;
        As[lq+4][lrow] = a1.x; As[lq+5][lrow] = a1.y; As[lq+6][lrow] = a1.z; As[lq+7][lrow] = a1.w;
        int kk = k0 + ty;
        #pragma unroll
        for (int q = 0; q < 8; q++) {
            int c = tx*8 + q;
            Bs[ty][c] = (c < OUTC) ? W3[(size_t)kk*OUTC + c] : 0.0f;
        }
        __syncthreads();
        #pragma unroll
        for (int k = 0; k < 16; k++) {
            float a[8], bv[8];
            *(float4*)(a)    = *(const float4*)&As[k][ty*8];
            *(float4*)(a+4)  = *(const float4*)&As[k][ty*8+4];
            *(float4*)(bv)   = *(const float4*)&Bs[k][tx*8];
            *(float4*)(bv+4) = *(const float4*)&Bs[k][tx*8+4];
            #pragma unroll
            for (int i = 0; i < 8; i++)
                #pragma unroll
                for (int j = 0; j < 8; j++)
                    acc[i][j] = fmaf(a[i], bv[j], acc[i][j]);
        }
        __syncthreads();
    }
    const float HRS = (float)(3.14159265359 / 12.0);
    #pragma unroll
    for (int i = 0; i < 8; i++) {
        int r = row0 + ty*8 + i;
        #pragma unroll
        for (int j = 0; j < 8; j++) {
            int c = tx*8 + j;
            if (c >= OUTC) continue;
            float v = acc[i][j] + sb3[c];
            if (c < 3)       out[O_CENTER + r*3 + c] = g_newxyz[r*3 + c] + v;
            else if (c < 5)  out[O_OBJ + r*2 + (c-3)] = v;
            else if (c < 17) out[O_HS + r*12 + (c-5)] = v;
            else if (c < 35) out[O_SS + r*18 + (c-17)] = v;
            else if (c < 47) { out[O_HRN + r*12 + (c-35)] = v; out[O_HR + r*12 + (c-35)] = v * HRS; }
            else if (c < 101){ int q = c - 47; out[O_SRN + r*54 + q] = v; out[O_SR + r*54 + q] = v * sms[q]; }
            else             out[O_SEM + r*18 + (c-101)] = v;
        }
    }
}

// ---------------- tail ----------------
__global__ void tail_kernel(float* __restrict__ out) {
    int i = blockIdx.x * 256 + threadIdx.x;
    if (i < NG*3) out[O_NEWXYZ + i] = g_newxyz[i];
    if (i < NG)   out[O_INDS + i] = (float)g_inds[i];
}

// ---------------- launch ----------------
extern "C" void kernel_launch(void* const* d_in, const int* in_sizes, int n_in,
                              void* d_out, int out_size) {
    const float* xyz      = (const float*)d_in[0];
    const float* features = (const float*)d_in[1];
    const float* msz      = (const float*)d_in[2];
    const float* w0  = (const float*)d_in[3];
    const float* b0  = (const float*)d_in[4];
    const float* gm0 = (const float*)d_in[5];
    const float* be0 = (const float*)d_in[6];
    const float* wm1 = (const float*)d_in[7];
    const float* bm1 = (const float*)d_in[8];
    const float* gm1 = (const float*)d_in[9];
    const float* bem1= (const float*)d_in[10];
    const float* wm2 = (const float*)d_in[11];
    const float* bm2 = (const float*)d_in[12];
    const float* gm2 = (const float*)d_in[13];
    const float* bem2= (const float*)d_in[14];
    const float* w1  = (const float*)d_in[15];
    const float* b1  = (const float*)d_in[16];
    const float* g1  = (const float*)d_in[17];
    const float* be1 = (const float*)d_in[18];
    const float* w2  = (const float*)d_in[19];
    const float* b2  = (const float*)d_in[20];
    const float* g2  = (const float*)d_in[21];
    const float* be2 = (const float*)d_in[22];
    const float* w3  = (const float*)d_in[23];
    const float* b3  = (const float*)d_in[24];
    float* out = (float*)d_out;

    fps_kernel<<<BB, 1024>>>(xyz);
    ballquery_kernel<<<BB, 256>>>(xyz);
    prep_w0<<<(288*128 + 255)/256, 256>>>(w0);
    prep_w128<<<64, 256>>>(wm1, 1);
    prep_w128<<<64, 256>>>(wm2, 2);
    mma_layer0_kernel<<<NROWS/128, 256>>>(xyz, features, b0, gm0, be0);
    mma_gemm_kernel<<<NROWS/128, 256>>>(1, bm1, gm1, bem1);
    mma_gemm_kernel<<<NROWS/128, 256>>>(2, bm2, gm2, bem2);
    maxpool_kernel<<<(NG*HID)/256, 256>>>();
    gemm128_kernel<1><<<NG/128, 256>>>(1, w1, b1, g1, be1, 2);
    gemm128_kernel<1><<<NG/128, 256>>>(2, w2, b2, g2, be2, 2);
    head_kernel<<<NG/128, 256>>>(w3, b3, msz, out);
    tail_kernel<<<(NG*3 + 255)/256, 256>>>(out);
}

// round 4
// speedup vs baseline: 1.5483x; 1.1346x over previous
#include <cuda_runtime.h>
#include <cstdint>

#define BB    32
#define KK    1024
#define CC    256
#define PP    256
#define NSAMP 16
#define NROWS (BB*PP*NSAMP)   // 131072
#define NG    (BB*PP)         // 8192
#define HID   128
#define OUTC  119

// output segment offsets (floats): obj, center, hs, hrn, hr, ss, srn, sr, sem, new_xyz, inds
#define O_OBJ    0
#define O_CENTER 16384
#define O_HS     40960
#define O_HRN    139264
#define O_HR     237568
#define O_SS     335872
#define O_SRN    483328
#define O_SR     925696
#define O_SEM    1368064
#define O_NEWXYZ 1515520
#define O_INDS   1540096

// ---------------- scratch ----------------
__device__ int   g_inds[NG];
__device__ float g_newxyz[NG*3];
__device__ int   g_idx[NROWS];
__device__ __align__(16) float g_feat[NG*HID];
__device__ __align__(16) float g_n1[NG*HID];
// weights in B-fragment layout: ((k_tile*16 + n_tile)*32 + lane)*2 + slot
__device__ __align__(16) float g_w0f[36*16*64];   // K=288 (36 k_tiles), zero-padded
__device__ __align__(16) float g_w1f[16*16*64];
__device__ __align__(16) float g_w2f[16*16*64];

__device__ __forceinline__ float* bufsel(int w) {
    if (w == 1) return g_feat;
    return g_n1;
}

__device__ __forceinline__ float tf32r(float v) {
    float o;
    asm("cvt.rna.tf32.f32 %0, %1;" : "=f"(o) : "f"(v));
    return o;
}

// mma.sync m16n8k8 tf32: D += A*B
__device__ __forceinline__ void mma8(float c[4], const float a[4], float b0, float b1) {
    asm volatile(
        "mma.sync.aligned.m16n8k8.row.col.f32.tf32.tf32.f32 "
        "{%0,%1,%2,%3}, {%4,%5,%6,%7}, {%8,%9}, {%0,%1,%2,%3};\n"
        : "+f"(c[0]), "+f"(c[1]), "+f"(c[2]), "+f"(c[3])
        : "r"(__float_as_uint(a[0])), "r"(__float_as_uint(a[1])),
          "r"(__float_as_uint(a[2])), "r"(__float_as_uint(a[3])),
          "r"(__float_as_uint(b0)), "r"(__float_as_uint(b1)));
}

// ---------------- FPS ----------------
__global__ void fps_kernel(const float* __restrict__ xyz) {
    __shared__ float sx[KK], sy[KK], sz[KK];
    __shared__ float swv[32];
    __shared__ int   swi[32];
    __shared__ int   s_last;
    const int b = blockIdx.x;
    const int t = threadIdx.x;
    const float* xb = xyz + (size_t)b * KK * 3;
    float x = xb[t*3+0], y = xb[t*3+1], z = xb[t*3+2];
    sx[t] = x; sy[t] = y; sz[t] = z;
    if (t == 0) {
        g_inds[b*PP] = 0;
        g_newxyz[(b*PP)*3+0] = x; g_newxyz[(b*PP)*3+1] = y; g_newxyz[(b*PP)*3+2] = z;
    }
    __syncthreads();
    float dist = 1e10f;
    int last = 0;
    for (int it = 1; it < PP; it++) {
        float dx = x - sx[last], dy = y - sy[last], dz = z - sz[last];
        float d = fmaf(dz, dz, fmaf(dy, dy, dx*dx));
        dist = fminf(dist, d);
        float v = dist; int idx = t;
        #pragma unroll
        for (int o = 16; o > 0; o >>= 1) {
            float v2 = __shfl_down_sync(0xffffffffu, v, o);
            int   i2 = __shfl_down_sync(0xffffffffu, idx, o);
            if (v2 > v || (v2 == v && i2 < idx)) { v = v2; idx = i2; }
        }
        if ((t & 31) == 0) { swv[t>>5] = v; swi[t>>5] = idx; }
        __syncthreads();
        if (t < 32) {
            v = swv[t]; idx = swi[t];
            #pragma unroll
            for (int o = 16; o > 0; o >>= 1) {
                float v2 = __shfl_down_sync(0xffffffffu, v, o);
                int   i2 = __shfl_down_sync(0xffffffffu, idx, o);
                if (v2 > v || (v2 == v && i2 < idx)) { v = v2; idx = i2; }
            }
            if (t == 0) {
                s_last = idx;
                g_inds[b*PP + it] = idx;
                g_newxyz[(b*PP + it)*3+0] = sx[idx];
                g_newxyz[(b*PP + it)*3+1] = sy[idx];
                g_newxyz[(b*PP + it)*3+2] = sz[idx];
            }
        }
        __syncthreads();
        last = s_last;
    }
}

// ---------------- ball query ----------------
__global__ void ballquery_kernel(const float* __restrict__ xyz) {
    __shared__ float sx[KK], sy[KK], sz[KK];
    const int b = blockIdx.x;
    const int t = threadIdx.x;
    const float* xb = xyz + (size_t)b * KK * 3;
    for (int i = t; i < KK; i += 256) { sx[i] = xb[i*3+0]; sy[i] = xb[i*3+1]; sz[i] = xb[i*3+2]; }
    __syncthreads();
    const int gp = b*PP + t;
    float nx = g_newxyz[gp*3+0], ny = g_newxyz[gp*3+1], nz = g_newxyz[gp*3+2];
    int buf[NSAMP]; int cnt = 0;
    for (int j = 0; j < KK; j++) {
        float dx = nx - sx[j], dy = ny - sy[j], dz = nz - sz[j];
        float d = fmaf(dz, dz, fmaf(dy, dy, dx*dx));
        if (d < 0.09f) { if (cnt < NSAMP) buf[cnt] = j; cnt++; }
    }
    if (cnt == 0) { for (int s = 0; s < NSAMP; s++) buf[s] = KK - 1; }
    else { int c = cnt < NSAMP ? cnt : NSAMP; for (int s = c; s < NSAMP; s++) buf[s] = buf[0]; }
    #pragma unroll
    for (int s = 0; s < NSAMP; s++) g_idx[gp*NSAMP + s] = buf[s];
}

// ---------------- weight prep: [k][n] -> B-fragment layout ----------------
__global__ void prep_w0f(const float* __restrict__ w) {   // w: [259][128] -> 288 k padded
    int i = blockIdx.x * 256 + threadIdx.x;                // over 288*128
    if (i >= 288*128) return;
    int k = i >> 7, n = i & 127;
    float v = (k < 259) ? tf32r(w[i]) : 0.0f;
    int kt = k >> 3, kin = k & 7, ntl = n >> 3, gq = n & 7;
    int lane = gq*4 + (kin & 3), slot = kin >> 2;
    g_w0f[((kt*16 + ntl)*32 + lane)*2 + slot] = v;
}
__global__ void prep_w128f(const float* __restrict__ w, int which) {  // [128][128]
    int i = blockIdx.x * 256 + threadIdx.x;
    int k = i >> 7, n = i & 127;
    float v = tf32r(w[i]);
    int kt = k >> 3, kin = k & 7, ntl = n >> 3, gq = n & 7;
    int lane = gq*4 + (kin & 3), slot = kin >> 2;
    float* dst = (which == 1) ? g_w1f : g_w2f;
    dst[((kt*16 + ntl)*32 + lane)*2 + slot] = v;
}

// epilogue: affine+relu+tf32 -> A-fragment layout of dst, then zero acc
__device__ __forceinline__ void epi_store(float* dst, float acc[2][8][4],
                                          const float* sgp, const float* sbp, const float* sep,
                                          int warp_m, int warp_n, int grp, int tig) {
    const int la0 = grp*4 + ((2*tig) & 3);
    const int slot_hi = (tig < 2) ? 0 : 2;
    #pragma unroll
    for (int mt = 0; mt < 2; mt++) {
        int m_tile = warp_m*2 + mt;
        #pragma unroll
        for (int nt = 0; nt < 8; nt++) {
            int c = warp_n*64 + nt*8 + tig*2;
            float ga = sgp[c], gb = sgp[c+1], ba = sbp[c], bb = sbp[c+1], ea = sep[c], eb = sep[c+1];
            float v0 = tf32r(fmaxf(fmaf(ga, acc[mt][nt][0] + ba, ea), 0.0f));
            float v1 = tf32r(fmaxf(fmaf(gb, acc[mt][nt][1] + bb, eb), 0.0f));
            float v2 = tf32r(fmaxf(fmaf(ga, acc[mt][nt][2] + ba, ea), 0.0f));
            float v3 = tf32r(fmaxf(fmaf(gb, acc[mt][nt][3] + bb, eb), 0.0f));
            int kt = warp_n*8 + nt;
            float* p = dst + (m_tile*16 + kt)*128 + la0*4 + slot_hi;
            *(float2*)p       = make_float2(v0, v2);
            *(float2*)(p + 4) = make_float2(v1, v3);
            acc[mt][nt][0] = 0.f; acc[mt][nt][1] = 0.f; acc[mt][nt][2] = 0.f; acc[mt][nt][3] = 0.f;
        }
    }
}

// run one K=128 GEMM from A-fragment smem + staged B-fragment smem
__device__ __forceinline__ void mma_128(const float* Af, const float* Bst,
                                        float acc[2][8][4],
                                        int warp_m, int warp_n, int lane) {
    #pragma unroll
    for (int ks = 0; ks < 16; ks++) {
        float4 a0 = *(const float4*)&Af[((warp_m*2 + 0)*16 + ks)*128 + lane*4];
        float4 a1 = *(const float4*)&Af[((warp_m*2 + 1)*16 + ks)*128 + lane*4];
        float2 bv[8];
        #pragma unroll
        for (int nt = 0; nt < 8; nt++)
            bv[nt] = *(const float2*)&Bst[((ks*16 + warp_n*8 + nt)*32 + lane)*2];
        #pragma unroll
        for (int nt = 0; nt < 8; nt++) {
            mma8(acc[0][nt], (const float*)&a0, bv[nt].x, bv[nt].y);
            mma8(acc[1][nt], (const float*)&a1, bv[nt].x, bv[nt].y);
        }
    }
}

// ---------------- fused layer0+1+2+maxpool ----------------
__global__ void fused_mlp_kernel(const float* __restrict__ xyz,
                                 const float* __restrict__ feats,
                                 const float* __restrict__ b0, const float* __restrict__ g0, const float* __restrict__ e0,
                                 const float* __restrict__ b1, const float* __restrict__ g1, const float* __restrict__ e1,
                                 const float* __restrict__ b2, const float* __restrict__ g2, const float* __restrict__ e2) {
    extern __shared__ float sm[];
    float* AfragA = sm;            // 16384 floats (64KB)
    float* AfragB = sm + 16384;    // 16384 floats (64KB) — also layer0 A-chunk buffer
    float* Bstage = sm + 32768;    // 16384 floats (64KB)
    __shared__ float sg[3][128], sb[3][128], se[3][128];
    __shared__ int   sj[128];
    __shared__ float sg3[128][3];

    const int tid = threadIdx.x, lane = tid & 31, wid = tid >> 5;
    const int warp_m = wid >> 1, warp_n = wid & 1;
    const int grp = lane >> 2, tig = lane & 3;
    const int tile = blockIdx.x, row0 = tile * 128;

    if (tid < 128) {
        sg[0][tid] = g0[tid]; sb[0][tid] = b0[tid]; se[0][tid] = e0[tid];
        sg[1][tid] = g1[tid]; sb[1][tid] = b1[tid]; se[1][tid] = e1[tid];
        sg[2][tid] = g2[tid]; sb[2][tid] = b2[tid]; se[2][tid] = e2[tid];
        int grow = row0 + tid;
        int b = grow >> 12;
        int p = (grow & 4095) >> 4;
        int j = g_idx[grow];
        sj[tid] = j;
        int gp = b * PP + p;
        #pragma unroll
        for (int d = 0; d < 3; d++)
            sg3[tid][d] = __fdiv_rn(xyz[(size_t)(b*KK + j)*3 + d] - g_newxyz[gp*3 + d], 0.3f);
    }
    __syncthreads();

    float acc[2][8][4];
    #pragma unroll
    for (int mt = 0; mt < 2; mt++)
        #pragma unroll
        for (int nt = 0; nt < 8; nt++)
            #pragma unroll
            for (int q = 0; q < 4; q++) acc[mt][nt][q] = 0.0f;

    // ---- layer 0: K=288 in 9 chunks of 32 ----
    const int ar = tid >> 1, h = tid & 1;
    const float* frow = feats + (size_t)((row0 >> 12) * KK + sj[ar]) * CC;
    const int m_tile_f = ar >> 4;
    const int R = ar & 15;
    const int laneBase = (R & 7) * 4;
    const int slotR = (R < 8) ? 0 : 1;

    for (int c9 = 0; c9 < 9; c9++) {
        int kc = c9 * 32;
        // fill gathered A chunk (frag layout) into AfragB
        #pragma unroll
        for (int q = 0; q < 16; q++) {
            int kl = h*16 + q;
            int k = kc + kl;
            float v;
            if (k < 3)        v = sg3[ar][k];
            else if (k < 259) v = __ldg(frow + k - 3);
            else              v = 0.0f;
            int ktl = kl >> 3, kin = kl & 7;
            AfragB[(m_tile_f*4 + ktl)*128 + (laneBase + (kin & 3))*4 + slotR + ((kin < 4) ? 0 : 2)] = tf32r(v);
        }
        // stage B chunk (16KB contiguous)
        {
            const float4* src = (const float4*)(g_w0f + c9 * 4096);
            float4* dst = (float4*)Bstage;
            #pragma unroll
            for (int q = 0; q < 4; q++) dst[tid + q*256] = src[tid + q*256];
        }
        __syncthreads();
        // mma over 4 k_tiles
        #pragma unroll
        for (int ks = 0; ks < 4; ks++) {
            float4 a0 = *(const float4*)&AfragB[((warp_m*2 + 0)*4 + ks)*128 + lane*4];
            float4 a1 = *(const float4*)&AfragB[((warp_m*2 + 1)*4 + ks)*128 + lane*4];
            float2 bv[8];
            #pragma unroll
            for (int nt = 0; nt < 8; nt++)
                bv[nt] = *(const float2*)&Bstage[((ks*16 + warp_n*8 + nt)*32 + lane)*2];
            #pragma unroll
            for (int nt = 0; nt < 8; nt++) {
                mma8(acc[0][nt], (const float*)&a0, bv[nt].x, bv[nt].y);
                mma8(acc[1][nt], (const float*)&a1, bv[nt].x, bv[nt].y);
            }
        }
        __syncthreads();
    }
    // epilogue0 -> AfragA
    epi_store(AfragA, acc, sg[0], sb[0], se[0], warp_m, warp_n, grp, tig);
    __syncthreads();

    // ---- layer 1 ----
    {
        const float4* src = (const float4*)g_w1f;
        float4* dst = (float4*)Bstage;
        #pragma unroll
        for (int q = 0; q < 16; q++) dst[tid + q*256] = src[tid + q*256];
    }
    __syncthreads();
    mma_128(AfragA, Bstage, acc, warp_m, warp_n, lane);
    epi_store(AfragB, acc, sg[1], sb[1], se[1], warp_m, warp_n, grp, tig);
    __syncthreads();

    // ---- layer 2 ----
    {
        const float4* src = (const float4*)g_w2f;
        float4* dst = (float4*)Bstage;
        #pragma unroll
        for (int q = 0; q < 16; q++) dst[tid + q*256] = src[tid + q*256];
    }
    __syncthreads();
    mma_128(AfragB, Bstage, acc, warp_m, warp_n, lane);

    // ---- maxpool epilogue: 16-row groups == one mt tile ----
    #pragma unroll
    for (int mt = 0; mt < 2; mt++) {
        int gidx = tile*8 + warp_m*2 + mt;
        #pragma unroll
        for (int nt = 0; nt < 8; nt++) {
            int c = warp_n*64 + nt*8 + tig*2;
            float ga = sg[2][c], gb = sg[2][c+1], ba = sb[2][c], bb = sb[2][c+1], ea = se[2][c], eb = se[2][c+1];
            float v0 = fmaxf(fmaf(ga, acc[mt][nt][0] + ba, ea), 0.0f);
            float v1 = fmaxf(fmaf(gb, acc[mt][nt][1] + bb, eb), 0.0f);
            float v2 = fmaxf(fmaf(ga, acc[mt][nt][2] + ba, ea), 0.0f);
            float v3 = fmaxf(fmaf(gb, acc[mt][nt][3] + bb, eb), 0.0f);
            float mA = fmaxf(v0, v2), mB = fmaxf(v1, v3);
            #pragma unroll
            for (int o = 4; o < 32; o <<= 1) {
                mA = fmaxf(mA, __shfl_xor_sync(0xffffffffu, mA, o));
                mB = fmaxf(mB, __shfl_xor_sync(0xffffffffu, mB, o));
            }
            if (grp == 0) {
                g_feat[(size_t)gidx*128 + c]     = mA;
                g_feat[(size_t)gidx*128 + c + 1] = mB;
            }
        }
    }
}

// ---------------- fp32 SGEMM for FC layers (rows=8192, K=128) ----------------
template<int ACT>
__global__ void gemm128_kernel(int abuf, const float* __restrict__ W,
                               const float* __restrict__ bias,
                               const float* __restrict__ gam,
                               const float* __restrict__ bet,
                               int ybuf) {
    const float* A = bufsel(abuf);
    float* Y = bufsel(ybuf);
    __shared__ float As[16][128];
    __shared__ float Bs[16][128];
    const int t = threadIdx.x;
    const int tx = t & 15, ty = t >> 4;
    const int row0 = blockIdx.x * 128;
    const int lrow = t >> 1, lq = (t & 1) * 8;
    float acc[8][8];
    #pragma unroll
    for (int i = 0; i < 8; i++)
        #pragma unroll
        for (int j = 0; j < 8; j++) acc[i][j] = 0.0f;
    for (int k0 = 0; k0 < 128; k0 += 16) {
        float4 a0 = *(const float4*)(A + (size_t)(row0+lrow)*128 + k0 + lq);
        float4 a1 = *(const float4*)(A + (size_t)(row0+lrow)*128 + k0 + lq + 4);
        As[lq+0][lrow] = a0.x; As[lq+1][lrow] = a0.y; As[lq+2][lrow] = a0.z; As[lq+3][lrow] = a0.w;
        As[lq+4][lrow] = a1.x; As[lq+5][lrow] = a1.y; As[lq+6][lrow] = a1.z; As[lq+7][lrow] = a1.w;
        *(float4*)&Bs[ty][tx*8]     = *(const float4*)(W + (size_t)(k0+ty)*128 + tx*8);
        *(float4*)&Bs[ty][tx*8 + 4] = *(const float4*)(W + (size_t)(k0+ty)*128 + tx*8 + 4);
        __syncthreads();
        #pragma unroll
        for (int k = 0; k < 16; k++) {
            float a[8], bv[8];
            *(float4*)(a)    = *(const float4*)&As[k][ty*8];
            *(float4*)(a+4)  = *(const float4*)&As[k][ty*8+4];
            *(float4*)(bv)   = *(const float4*)&Bs[k][tx*8];
            *(float4*)(bv+4) = *(const float4*)&Bs[k][tx*8+4];
            #pragma unroll
            for (int i = 0; i < 8; i++)
                #pragma unroll
                for (int j = 0; j < 8; j++)
                    acc[i][j] = fmaf(a[i], bv[j], acc[i][j]);
        }
        __syncthreads();
    }
    float gj[8], bj[8], ej[8];
    #pragma unroll
    for (int j = 0; j < 8; j++) { int c = tx*8 + j; gj[j] = gam[c]; bj[j] = bias[c]; ej[j] = bet[c]; }
    #pragma unroll
    for (int i = 0; i < 8; i++) {
        int r = row0 + ty*8 + i;
        float vv[8];
        #pragma unroll
        for (int j = 0; j < 8; j++) {
            float v = fmaf(gj[j], acc[i][j] + bj[j], ej[j]);
            v = fmaxf(v, 0.0f);
            if (ACT == 1) v = fminf(v, 6.0f);
            vv[j] = v;
        }
        *(float4*)(Y + (size_t)r*128 + tx*8)     = make_float4(vv[0],vv[1],vv[2],vv[3]);
        *(float4*)(Y + (size_t)r*128 + tx*8 + 4) = make_float4(vv[4],vv[5],vv[6],vv[7]);
    }
}

// ---------------- head ----------------
__global__ void head_kernel(const float* __restrict__ W3,
                            const float* __restrict__ b3,
                            const float* __restrict__ msz,
                            float* __restrict__ out) {
    const float* A = g_n1;
    __shared__ float As[16][128];
    __shared__ float Bs[16][128];
    __shared__ float sb3[OUTC];
    __shared__ float sms[54];
    const int t = threadIdx.x;
    const int tx = t & 15, ty = t >> 4;
    const int row0 = blockIdx.x * 128;
    const int lrow = t >> 1, lq = (t & 1) * 8;
    if (t < OUTC) sb3[t] = b3[t];
    if (t >= 128 && t < 128 + 54) sms[t - 128] = msz[t - 128];
    float acc[8][8];
    #pragma unroll
    for (int i = 0; i < 8; i++)
        #pragma unroll
        for (int j = 0; j < 8; j++) acc[i][j] = 0.0f;
    for (int k0 = 0; k0 < 128; k0 += 16) {
        float4 a0 = *(const float4*)(A + (size_t)(row0+lrow)*128 + k0 + lq);
        float4 a1 = *(const float4*)(A + (size_t)(row0+lrow)*128 + k0 + lq + 4);
        As[lq+0][lrow] = a0.x; As[lq+1][lrow] = a0.y; As[lq+2][lrow] = a0.z; As[lq+3][lrow] = a0.w;
        As[lq+4][lrow] = a1.x; As[lq+5][lrow] = a1.y; As[lq+6][lrow] = a1.z; As[lq+7][lrow] = a1.w;
        int kk = k0 + ty;
        #pragma unroll
        for (int q = 0; q < 8; q++) {
            int c = tx*8 + q;
            Bs[ty][c] = (c < OUTC) ? W3[(size_t)kk*OUTC + c] : 0.0f;
        }
        __syncthreads();
        #pragma unroll
        for (int k = 0; k < 16; k++) {
            float a[8], bv[8];
            *(float4*)(a)    = *(const float4*)&As[k][ty*8];
            *(float4*)(a+4)  = *(const float4*)&As[k][ty*8+4];
            *(float4*)(bv)   = *(const float4*)&Bs[k][tx*8];
            *(float4*)(bv+4) = *(const float4*)&Bs[k][tx*8+4];
            #pragma unroll
            for (int i = 0; i < 8; i++)
                #pragma unroll
                for (int j = 0; j < 8; j++)
                    acc[i][j] = fmaf(a[i], bv[j], acc[i][j]);
        }
        __syncthreads();
    }
    const float HRS = (float)(3.14159265359 / 12.0);
    #pragma unroll
    for (int i = 0; i < 8; i++) {
        int r = row0 + ty*8 + i;
        #pragma unroll
        for (int j = 0; j < 8; j++) {
            int c = tx*8 + j;
            if (c >= OUTC) continue;
            float v = acc[i][j] + sb3[c];
            if (c < 3)       out[O_CENTER + r*3 + c] = g_newxyz[r*3 + c] + v;
            else if (c < 5)  out[O_OBJ + r*2 + (c-3)] = v;
            else if (c < 17) out[O_HS + r*12 + (c-5)] = v;
            else if (c < 35) out[O_SS + r*18 + (c-17)] = v;
            else if (c < 47) { out[O_HRN + r*12 + (c-35)] = v; out[O_HR + r*12 + (c-35)] = v * HRS; }
            else if (c < 101){ int q = c - 47; out[O_SRN + r*54 + q] = v; out[O_SR + r*54 + q] = v * sms[q]; }
            else             out[O_SEM + r*18 + (c-101)] = v;
        }
    }
}

// ---------------- tail ----------------
__global__ void tail_kernel(float* __restrict__ out) {
    int i = blockIdx.x * 256 + threadIdx.x;
    if (i < NG*3) out[O_NEWXYZ + i] = g_newxyz[i];
    if (i < NG)   out[O_INDS + i] = (float)g_inds[i];
}

// ---------------- launch ----------------
extern "C" void kernel_launch(void* const* d_in, const int* in_sizes, int n_in,
                              void* d_out, int out_size) {
    const float* xyz      = (const float*)d_in[0];
    const float* features = (const float*)d_in[1];
    const float* msz      = (const float*)d_in[2];
    const float* w0  = (const float*)d_in[3];
    const float* b0  = (const float*)d_in[4];
    const float* gm0 = (const float*)d_in[5];
    const float* be0 = (const float*)d_in[6];
    const float* wm1 = (const float*)d_in[7];
    const float* bm1 = (const float*)d_in[8];
    const float* gm1 = (const float*)d_in[9];
    const float* bem1= (const float*)d_in[10];
    const float* wm2 = (const float*)d_in[11];
    const float* bm2 = (const float*)d_in[12];
    const float* gm2 = (const float*)d_in[13];
    const float* bem2= (const float*)d_in[14];
    const float* w1  = (const float*)d_in[15];
    const float* b1  = (const float*)d_in[16];
    const float* g1  = (const float*)d_in[17];
    const float* be1 = (const float*)d_in[18];
    const float* w2  = (const float*)d_in[19];
    const float* b2  = (const float*)d_in[20];
    const float* g2  = (const float*)d_in[21];
    const float* be2 = (const float*)d_in[22];
    const float* w3  = (const float*)d_in[23];
    const float* b3  = (const float*)d_in[24];
    float* out = (float*)d_out;

    cudaFuncSetAttribute(fused_mlp_kernel, cudaFuncAttributeMaxDynamicSharedMemorySize, 196608);

    fps_kernel<<<BB, 1024>>>(xyz);
    ballquery_kernel<<<BB, 256>>>(xyz);
    prep_w0f<<<(288*128 + 255)/256, 256>>>(w0);
    prep_w128f<<<64, 256>>>(wm1, 1);
    prep_w128f<<<64, 256>>>(wm2, 2);
    fused_mlp_kernel<<<NROWS/128, 256, 196608>>>(xyz, features,
                                                 b0, gm0, be0,
                                                 bm1, gm1, bem1,
                                                 bm2, gm2, bem2);
    gemm128_kernel<1><<<NG/128, 256>>>(1, w1, b1, g1, be1, 2);
    gemm128_kernel<1><<<NG/128, 256>>>(2, w2, b2, g2, be2, 2);
    head_kernel<<<NG/128, 256>>>(w3, b3, msz, out);
    tail_kernel<<<(NG*3 + 255)/256, 256>>>(out);
}

// round 6
// speedup vs baseline: 2.0432x; 1.3197x over previous
#include <cuda_runtime.h>
#include <cstdint>

#define BB    32
#define KK    1024
#define CC    256
#define PP    256
#define NSAMP 16
#define NROWS (BB*PP*NSAMP)   // 131072
#define NG    (BB*PP)         // 8192
#define HID   128
#define OUTC  119

// output segment offsets (floats): obj, center, hs, hrn, hr, ss, srn, sr, sem, new_xyz, inds
#define O_OBJ    0
#define O_CENTER 16384
#define O_HS     40960
#define O_HRN    139264
#define O_HR     237568
#define O_SS     335872
#define O_SRN    483328
#define O_SR     925696
#define O_SEM    1368064
#define O_NEWXYZ 1515520
#define O_INDS   1540096

// ---------------- scratch ----------------
__device__ int   g_inds[NG];
__device__ float g_newxyz[NG*3];
__device__ int   g_idx[NROWS];
__device__ __align__(16) float g_feat[NG*HID];
// weights in B-fragment layout: ((k_tile*16 + n_tile)*32 + lane)*2 + slot
__device__ __align__(16) float g_w0f[36*16*64];   // layer0, K permuted: feats k=0..255, xyz k=256..258
__device__ __align__(16) float g_w1f[16*16*64];
__device__ __align__(16) float g_w2f[16*16*64];
__device__ __align__(16) float g_fw1f[16*16*64];  // FC1
__device__ __align__(16) float g_fw2f[16*16*64];  // FC2
__device__ __align__(16) float g_fw3f[16*16*64];  // head (N padded 119->128)

__device__ __forceinline__ float tf32r(float v) {
    float o;
    asm("cvt.rna.tf32.f32 %0, %1;" : "=f"(o) : "f"(v));
    return o;
}

// mma.sync m16n8k8 tf32: D += A*B
__device__ __forceinline__ void mma8(float c[4], const float a[4], float b0, float b1) {
    asm volatile(
        "mma.sync.aligned.m16n8k8.row.col.f32.tf32.tf32.f32 "
        "{%0,%1,%2,%3}, {%4,%5,%6,%7}, {%8,%9}, {%0,%1,%2,%3};\n"
        : "+f"(c[0]), "+f"(c[1]), "+f"(c[2]), "+f"(c[3])
        : "r"(__float_as_uint(a[0])), "r"(__float_as_uint(a[1])),
          "r"(__float_as_uint(a[2])), "r"(__float_as_uint(a[3])),
          "r"(__float_as_uint(b0)), "r"(__float_as_uint(b1)));
}

// B-fragment scatter address for (k, n)
__device__ __forceinline__ void bfrag_store(float* dst, int k, int n, float v) {
    int kt = k >> 3, kin = k & 7, ntl = n >> 3, gq = n & 7;
    int lane = gq*4 + (kin & 3), slot = kin >> 2;
    dst[((kt*16 + ntl)*32 + lane)*2 + slot] = v;
}

// ---------------- FPS (blocks 0..31) + weight prep (blocks 32..147) ----------------
__global__ void fps_prep_kernel(const float* __restrict__ xyz,
                                const float* __restrict__ w0,
                                const float* __restrict__ wm1,
                                const float* __restrict__ wm2,
                                const float* __restrict__ w1,
                                const float* __restrict__ w2,
                                const float* __restrict__ w3) {
    __shared__ float sx[KK], sy[KK], sz[KK];
    __shared__ float swv[32];
    __shared__ int   swi[32];
    __shared__ int   s_last;

    if (blockIdx.x >= 32) {
        // ---- weight prep: 116 blocks x 1024 threads over 118784 elements ----
        int i = (blockIdx.x - 32) * 1024 + threadIdx.x;
        if (i < 36864) {
            // w0 permuted + padded: dst k<256 <- src k+3 ; dst 256..258 <- src 0..2 ; else 0
            int kd = i >> 7, n = i & 127;
            float v = 0.0f;
            if (kd < 256)      v = tf32r(w0[(size_t)(kd + 3)*128 + n]);
            else if (kd < 259) v = tf32r(w0[(size_t)(kd - 256)*128 + n]);
            bfrag_store(g_w0f, kd, n, v);
        } else if (i < 53248) {
            int j = i - 36864; int k = j >> 7, n = j & 127;
            bfrag_store(g_w1f, k, n, tf32r(wm1[j]));
        } else if (i < 69632) {
            int j = i - 53248; int k = j >> 7, n = j & 127;
            bfrag_store(g_w2f, k, n, tf32r(wm2[j]));
        } else if (i < 86016) {
            int j = i - 69632; int k = j >> 7, n = j & 127;
            bfrag_store(g_fw1f, k, n, tf32r(w1[j]));
        } else if (i < 102400) {
            int j = i - 86016; int k = j >> 7, n = j & 127;
            bfrag_store(g_fw2f, k, n, tf32r(w2[j]));
        } else if (i < 118784) {
            int j = i - 102400; int k = j >> 7, n = j & 127;
            float v = (n < OUTC) ? tf32r(w3[(size_t)k*OUTC + n]) : 0.0f;
            bfrag_store(g_fw3f, k, n, v);
        }
        return;
    }

    const int b = blockIdx.x;
    const int t = threadIdx.x;
    const float* xb = xyz + (size_t)b * KK * 3;
    float x = xb[t*3+0], y = xb[t*3+1], z = xb[t*3+2];
    sx[t] = x; sy[t] = y; sz[t] = z;
    if (t == 0) {
        g_inds[b*PP] = 0;
        g_newxyz[(b*PP)*3+0] = x; g_newxyz[(b*PP)*3+1] = y; g_newxyz[(b*PP)*3+2] = z;
    }
    __syncthreads();
    float dist = 1e10f;
    int last = 0;
    for (int it = 1; it < PP; it++) {
        float dx = x - sx[last], dy = y - sy[last], dz = z - sz[last];
        float d = fmaf(dz, dz, fmaf(dy, dy, dx*dx));
        dist = fminf(dist, d);
        float v = dist; int idx = t;
        #pragma unroll
        for (int o = 16; o > 0; o >>= 1) {
            float v2 = __shfl_down_sync(0xffffffffu, v, o);
            int   i2 = __shfl_down_sync(0xffffffffu, idx, o);
            if (v2 > v || (v2 == v && i2 < idx)) { v = v2; idx = i2; }
        }
        if ((t & 31) == 0) { swv[t>>5] = v; swi[t>>5] = idx; }
        __syncthreads();
        if (t < 32) {
            v = swv[t]; idx = swi[t];
            #pragma unroll
            for (int o = 16; o > 0; o >>= 1) {
                float v2 = __shfl_down_sync(0xffffffffu, v, o);
                int   i2 = __shfl_down_sync(0xffffffffu, idx, o);
                if (v2 > v || (v2 == v && i2 < idx)) { v = v2; idx = i2; }
            }
            if (t == 0) {
                s_last = idx;
                g_inds[b*PP + it] = idx;
                g_newxyz[(b*PP + it)*3+0] = sx[idx];
                g_newxyz[(b*PP + it)*3+1] = sy[idx];
                g_newxyz[(b*PP + it)*3+2] = sz[idx];
            }
        }
        __syncthreads();
        last = s_last;
    }
}

// ---------------- ball query ----------------
__global__ void ballquery_kernel(const float* __restrict__ xyz) {
    __shared__ float sx[KK], sy[KK], sz[KK];
    const int b = blockIdx.x;
    const int t = threadIdx.x;
    const float* xb = xyz + (size_t)b * KK * 3;
    for (int i = t; i < KK; i += 256) { sx[i] = xb[i*3+0]; sy[i] = xb[i*3+1]; sz[i] = xb[i*3+2]; }
    __syncthreads();
    const int gp = b*PP + t;
    float nx = g_newxyz[gp*3+0], ny = g_newxyz[gp*3+1], nz = g_newxyz[gp*3+2];
    int buf[NSAMP]; int cnt = 0;
    for (int j = 0; j < KK; j++) {
        float dx = nx - sx[j], dy = ny - sy[j], dz = nz - sz[j];
        float d = fmaf(dz, dz, fmaf(dy, dy, dx*dx));
        if (d < 0.09f) { if (cnt < NSAMP) buf[cnt] = j; cnt++; }
    }
    if (cnt == 0) { for (int s = 0; s < NSAMP; s++) buf[s] = KK - 1; }
    else { int c = cnt < NSAMP ? cnt : NSAMP; for (int s = c; s < NSAMP; s++) buf[s] = buf[0]; }
    #pragma unroll
    for (int s = 0; s < NSAMP; s++) g_idx[gp*NSAMP + s] = buf[s];
}

// epilogue: affine + relu(/6) + tf32 -> A-fragment layout of dst, zero acc
template<int ACT>
__device__ __forceinline__ void epi_store(float* dst, float acc[2][8][4],
                                          const float* sgp, const float* sbp, const float* sep,
                                          int warp_m, int warp_n, int grp, int tig) {
    const int la0 = grp*4 + ((2*tig) & 3);
    const int slot_hi = (tig < 2) ? 0 : 2;
    #pragma unroll
    for (int mt = 0; mt < 2; mt++) {
        int m_tile = warp_m*2 + mt;
        #pragma unroll
        for (int nt = 0; nt < 8; nt++) {
            int c = warp_n*64 + nt*8 + tig*2;
            float ga = sgp[c], gb = sgp[c+1], ba = sbp[c], bb = sbp[c+1], ea = sep[c], eb = sep[c+1];
            float v0 = fmaxf(fmaf(ga, acc[mt][nt][0] + ba, ea), 0.0f);
            float v1 = fmaxf(fmaf(gb, acc[mt][nt][1] + bb, eb), 0.0f);
            float v2 = fmaxf(fmaf(ga, acc[mt][nt][2] + ba, ea), 0.0f);
            float v3 = fmaxf(fmaf(gb, acc[mt][nt][3] + bb, eb), 0.0f);
            if (ACT == 1) { v0 = fminf(v0, 6.0f); v1 = fminf(v1, 6.0f); v2 = fminf(v2, 6.0f); v3 = fminf(v3, 6.0f); }
            v0 = tf32r(v0); v1 = tf32r(v1); v2 = tf32r(v2); v3 = tf32r(v3);
            int kt = warp_n*8 + nt;
            float* p = dst + (m_tile*16 + kt)*128 + la0*4 + slot_hi;
            *(float2*)p       = make_float2(v0, v2);
            *(float2*)(p + 4) = make_float2(v1, v3);
            acc[mt][nt][0] = 0.f; acc[mt][nt][1] = 0.f; acc[mt][nt][2] = 0.f; acc[mt][nt][3] = 0.f;
        }
    }
}

// one K=128 GEMM from A-fragment smem + B-fragment smem
__device__ __forceinline__ void mma_128(const float* Af, const float* Bst,
                                        float acc[2][8][4],
                                        int warp_m, int warp_n, int lane) {
    #pragma unroll
    for (int ks = 0; ks < 16; ks++) {
        float4 a0 = *(const float4*)&Af[((warp_m*2 + 0)*16 + ks)*128 + lane*4];
        float4 a1 = *(const float4*)&Af[((warp_m*2 + 1)*16 + ks)*128 + lane*4];
        float2 bv[8];
        #pragma unroll
        for (int nt = 0; nt < 8; nt++)
            bv[nt] = *(const float2*)&Bst[((ks*16 + warp_n*8 + nt)*32 + lane)*2];
        #pragma unroll
        for (int nt = 0; nt < 8; nt++) {
            mma8(acc[0][nt], (const float*)&a0, bv[nt].x, bv[nt].y);
            mma8(acc[1][nt], (const float*)&a1, bv[nt].x, bv[nt].y);
        }
    }
}

// A-chunk fragment scatter (KT k_tiles per m_tile row-block)
// laneRow = R & 7, slotR = (R < 8) ? 0 : 1; kl0 must satisfy (kl0 & 3) == 0
template<int KT>
__device__ __forceinline__ void afrag_sts4(float* A, int m_tile, int kl0,
                                           int laneRow, int slotR, float4 v) {
    int ktl = kl0 >> 3;
    int kin0 = kl0 & 7;
    int base = (m_tile*KT + ktl)*128 + laneRow*16 + slotR + ((kin0 < 4) ? 0 : 2);
    A[base + 0]  = tf32r(v.x);
    A[base + 4]  = tf32r(v.y);
    A[base + 8]  = tf32r(v.z);
    A[base + 12] = tf32r(v.w);
}

// ---------------- fused layer0+1+2+maxpool ----------------
__global__ void fused_mlp_kernel(const float* __restrict__ xyz,
                                 const float* __restrict__ feats,
                                 const float* __restrict__ b0, const float* __restrict__ g0, const float* __restrict__ e0,
                                 const float* __restrict__ b1, const float* __restrict__ g1, const float* __restrict__ e1,
                                 const float* __restrict__ b2, const float* __restrict__ g2, const float* __restrict__ e2) {
    extern __shared__ float sm[];
    // phase L0: B0all = sm[0..36863], Ach0 = sm+36864, Ach1 = sm+40960  (176KB)
    // phase L1/L2: AfragA = sm[0..16383], AfragB = sm+16384, Bstage = sm+32768 (192KB)
    __shared__ float sg[3][128], sb[3][128], se[3][128];
    __shared__ int   sj[128];
    __shared__ float sg3[128][3];

    const int tid = threadIdx.x, lane = tid & 31, wid = tid >> 5;
    const int warp_m = wid >> 1, warp_n = wid & 1;
    const int grp = lane >> 2, tig = lane & 3;
    const int tile = blockIdx.x, row0 = tile * 128;

    if (tid < 128) {
        sg[0][tid] = g0[tid]; sb[0][tid] = b0[tid]; se[0][tid] = e0[tid];
        sg[1][tid] = g1[tid]; sb[1][tid] = b1[tid]; se[1][tid] = e1[tid];
        sg[2][tid] = g2[tid]; sb[2][tid] = b2[tid]; se[2][tid] = e2[tid];
        int grow = row0 + tid;
        int b = grow >> 12;
        int p = (grow & 4095) >> 4;
        int j = g_idx[grow];
        sj[tid] = j;
        int gp = b * PP + p;
        #pragma unroll
        for (int d = 0; d < 3; d++)
            sg3[tid][d] = __fdiv_rn(xyz[(size_t)(b*KK + j)*3 + d] - g_newxyz[gp*3 + d], 0.3f);
    }
    __syncthreads();   // sj ready

    // stage entire B0 (144KB)
    {
        const float4* src = (const float4*)g_w0f;
        float4* dst = (float4*)sm;
        #pragma unroll
        for (int q = 0; q < 36; q++) dst[tid + q*256] = src[tid + q*256];
    }

    const int ar = tid >> 1, h = tid & 1;
    const float4* frow4 = (const float4*)(feats + (size_t)((row0 >> 12) * KK + sj[ar]) * CC);
    const int m_tile_f = ar >> 4;
    const int R = ar & 15;
    const int laneRow = R & 7;
    const int slotR = (R < 8) ? 0 : 1;
    float* Ach[2] = { sm + 36864, sm + 40960 };

    // fill chunk 0 (features k=0..31, aligned float4)
    #pragma unroll
    for (int j = 0; j < 4; j++)
        afrag_sts4<4>(Ach[0], m_tile_f, h*16 + j*4, laneRow, slotR, frow4[h*4 + j]);
    __syncthreads();

    float acc[2][8][4];
    #pragma unroll
    for (int mt = 0; mt < 2; mt++)
        #pragma unroll
        for (int nt = 0; nt < 8; nt++)
            #pragma unroll
            for (int q = 0; q < 4; q++) acc[mt][nt][q] = 0.0f;

    // ---- layer 0: 9 chunks of K=32, double-buffered ----
    for (int c = 0; c <= 8; c++) {
        float4 nxt[4];
        if (c < 7) {
            #pragma unroll
            for (int j = 0; j < 4; j++) nxt[j] = frow4[(c+1)*8 + h*4 + j];
        }
        const float* Acur = Ach[c & 1];
        const float* Bc = sm + c * 4096;
        #pragma unroll
        for (int ks = 0; ks < 4; ks++) {
            float4 a0 = *(const float4*)&Acur[((warp_m*2 + 0)*4 + ks)*128 + lane*4];
            float4 a1 = *(const float4*)&Acur[((warp_m*2 + 1)*4 + ks)*128 + lane*4];
            float2 bv[8];
            #pragma unroll
            for (int nt = 0; nt < 8; nt++)
                bv[nt] = *(const float2*)&Bc[((ks*16 + warp_n*8 + nt)*32 + lane)*2];
            #pragma unroll
            for (int nt = 0; nt < 8; nt++) {
                mma8(acc[0][nt], (const float*)&a0, bv[nt].x, bv[nt].y);
                mma8(acc[1][nt], (const float*)&a1, bv[nt].x, bv[nt].y);
            }
        }
        if (c < 7) {
            float* Anx = Ach[(c+1) & 1];
            #pragma unroll
            for (int j = 0; j < 4; j++)
                afrag_sts4<4>(Anx, m_tile_f, h*16 + j*4, laneRow, slotR, nxt[j]);
        } else if (c == 7) {
            // chunk 8: xyz (k=256..258) + zeros
            float* Anx = Ach[0];
            #pragma unroll
            for (int j = 0; j < 4; j++) {
                float4 v;
                if (h == 0 && j == 0) v = make_float4(sg3[ar][0], sg3[ar][1], sg3[ar][2], 0.0f);
                else                  v = make_float4(0.f, 0.f, 0.f, 0.f);
                afrag_sts4<4>(Anx, m_tile_f, h*16 + j*4, laneRow, slotR, v);
            }
        }
        __syncthreads();
    }

    // epilogue0 -> AfragA (aliases B0all start; all reads done past final sync)
    epi_store<0>(sm, acc, sg[0], sb[0], se[0], warp_m, warp_n, grp, tig);
    // stage B1
    {
        const float4* src = (const float4*)g_w1f;
        float4* dst = (float4*)(sm + 32768);
        #pragma unroll
        for (int q = 0; q < 16; q++) dst[tid + q*256] = src[tid + q*256];
    }
    __syncthreads();

    // ---- layer 1 ----
    mma_128(sm, sm + 32768, acc, warp_m, warp_n, lane);
    epi_store<0>(sm + 16384, acc, sg[1], sb[1], se[1], warp_m, warp_n, grp, tig);
    __syncthreads();
    // stage B2
    {
        const float4* src = (const float4*)g_w2f;
        float4* dst = (float4*)(sm + 32768);
        #pragma unroll
        for (int q = 0; q < 16; q++) dst[tid + q*256] = src[tid + q*256];
    }
    __syncthreads();

    // ---- layer 2 ----
    mma_128(sm + 16384, sm + 32768, acc, warp_m, warp_n, lane);

    // ---- maxpool epilogue ----
    #pragma unroll
    for (int mt = 0; mt < 2; mt++) {
        int gidx = tile*8 + warp_m*2 + mt;
        #pragma unroll
        for (int nt = 0; nt < 8; nt++) {
            int c = warp_n*64 + nt*8 + tig*2;
            float ga = sg[2][c], gb = sg[2][c+1], ba = sb[2][c], bb = sb[2][c+1], ea = se[2][c], eb = se[2][c+1];
            float v0 = fmaxf(fmaf(ga, acc[mt][nt][0] + ba, ea), 0.0f);
            float v1 = fmaxf(fmaf(gb, acc[mt][nt][1] + bb, eb), 0.0f);
            float v2 = fmaxf(fmaf(ga, acc[mt][nt][2] + ba, ea), 0.0f);
            float v3 = fmaxf(fmaf(gb, acc[mt][nt][3] + bb, eb), 0.0f);
            float mA = fmaxf(v0, v2), mB = fmaxf(v1, v3);
            #pragma unroll
            for (int o = 4; o < 32; o <<= 1) {
                mA = fmaxf(mA, __shfl_xor_sync(0xffffffffu, mA, o));
                mB = fmaxf(mB, __shfl_xor_sync(0xffffffffu, mB, o));
            }
            if (grp == 0) {
                g_feat[(size_t)gidx*128 + c]     = mA;
                g_feat[(size_t)gidx*128 + c + 1] = mB;
            }
        }
    }
}

// ---------------- fused FC1+FC2+head ----------------
__global__ void fused_fc_kernel(const float* __restrict__ b1, const float* __restrict__ g1, const float* __restrict__ e1,
                                const float* __restrict__ b2, const float* __restrict__ g2, const float* __restrict__ e2,
                                const float* __restrict__ b3, const float* __restrict__ msz,
                                float* __restrict__ out) {
    extern __shared__ float sm[];
    // AfragA = sm, AfragB = sm+16384, Bstage = sm+32768
    __shared__ float sg1[128], sb1[128], se1[128], sg2[128], sb2[128], se2[128];
    __shared__ float sb3[128], sms[54];

    const int tid = threadIdx.x, lane = tid & 31, wid = tid >> 5;
    const int warp_m = wid >> 1, warp_n = wid & 1;
    const int grp = lane >> 2, tig = lane & 3;
    const int row0 = blockIdx.x * 128;

    if (tid < 128) {
        sg1[tid] = g1[tid]; sb1[tid] = b1[tid]; se1[tid] = e1[tid];
        sg2[tid] = g2[tid]; sb2[tid] = b2[tid]; se2[tid] = e2[tid];
        sb3[tid] = (tid < OUTC) ? b3[tid] : 0.0f;
    } else if (tid < 182) {
        sms[tid - 128] = msz[tid - 128];
    }

    // fill AfragA from g_feat (row-major, aligned)
    const int ar = tid >> 1, h = tid & 1;
    const int m_tile_f = ar >> 4;
    const int R = ar & 15;
    const int laneRow = R & 7;
    const int slotR = (R < 8) ? 0 : 1;
    {
        const float4* frow4 = (const float4*)(g_feat + (size_t)(row0 + ar) * 128);
        #pragma unroll
        for (int j = 0; j < 16; j++)
            afrag_sts4<16>(sm, m_tile_f, h*64 + j*4, laneRow, slotR, frow4[h*16 + j]);
    }
    // stage FC1 weights
    {
        const float4* src = (const float4*)g_fw1f;
        float4* dst = (float4*)(sm + 32768);
        #pragma unroll
        for (int q = 0; q < 16; q++) dst[tid + q*256] = src[tid + q*256];
    }
    __syncthreads();

    float acc[2][8][4];
    #pragma unroll
    for (int mt = 0; mt < 2; mt++)
        #pragma unroll
        for (int nt = 0; nt < 8; nt++)
            #pragma unroll
            for (int q = 0; q < 4; q++) acc[mt][nt][q] = 0.0f;

    mma_128(sm, sm + 32768, acc, warp_m, warp_n, lane);
    epi_store<1>(sm + 16384, acc, sg1, sb1, se1, warp_m, warp_n, grp, tig);
    __syncthreads();
    {
        const float4* src = (const float4*)g_fw2f;
        float4* dst = (float4*)(sm + 32768);
        #pragma unroll
        for (int q = 0; q < 16; q++) dst[tid + q*256] = src[tid + q*256];
    }
    __syncthreads();

    mma_128(sm + 16384, sm + 32768, acc, warp_m, warp_n, lane);
    epi_store<1>(sm, acc, sg2, sb2, se2, warp_m, warp_n, grp, tig);
    __syncthreads();
    {
        const float4* src = (const float4*)g_fw3f;
        float4* dst = (float4*)(sm + 32768);
        #pragma unroll
        for (int q = 0; q < 16; q++) dst[tid + q*256] = src[tid + q*256];
    }
    __syncthreads();

    mma_128(sm, sm + 32768, acc, warp_m, warp_n, lane);

    // head scatter from accumulator frags
    const float HRS = (float)(3.14159265359 / 12.0);
    #pragma unroll
    for (int mt = 0; mt < 2; mt++) {
        int rA = row0 + warp_m*32 + mt*16 + grp;
        #pragma unroll
        for (int nt = 0; nt < 8; nt++) {
            int c0 = warp_n*64 + nt*8 + tig*2;
            #pragma unroll
            for (int q = 0; q < 4; q++) {
                int c = c0 + (q & 1);
                int r = (q < 2) ? rA : rA + 8;
                if (c >= OUTC) continue;
                float v = acc[mt][nt][q] + sb3[c];
                if (c < 3)       out[O_CENTER + r*3 + c] = g_newxyz[r*3 + c] + v;
                else if (c < 5)  out[O_OBJ + r*2 + (c-3)] = v;
                else if (c < 17) out[O_HS + r*12 + (c-5)] = v;
                else if (c < 35) out[O_SS + r*18 + (c-17)] = v;
                else if (c < 47) { out[O_HRN + r*12 + (c-35)] = v; out[O_HR + r*12 + (c-35)] = v * HRS; }
                else if (c < 101){ int s = c - 47; out[O_SRN + r*54 + s] = v; out[O_SR + r*54 + s] = v * sms[s]; }
                else             out[O_SEM + r*18 + (c-101)] = v;
            }
        }
    }
}

// ---------------- tail ----------------
__global__ void tail_kernel(float* __restrict__ out) {
    int i = blockIdx.x * 256 + threadIdx.x;
    if (i < NG*3) out[O_NEWXYZ + i] = g_newxyz[i];
    if (i < NG)   out[O_INDS + i] = (float)g_inds[i];
}

// ---------------- launch ----------------
extern "C" void kernel_launch(void* const* d_in, const int* in_sizes, int n_in,
                              void* d_out, int out_size) {
    const float* xyz      = (const float*)d_in[0];
    const float* features = (const float*)d_in[1];
    const float* msz      = (const float*)d_in[2];
    const float* w0  = (const float*)d_in[3];
    const float* b0  = (const float*)d_in[4];
    const float* gm0 = (const float*)d_in[5];
    const float* be0 = (const float*)d_in[6];
    const float* wm1 = (const float*)d_in[7];
    const float* bm1 = (const float*)d_in[8];
    const float* gm1 = (const float*)d_in[9];
    const float* bem1= (const float*)d_in[10];
    const float* wm2 = (const float*)d_in[11];
    const float* bm2 = (const float*)d_in[12];
    const float* gm2 = (const float*)d_in[13];
    const float* bem2= (const float*)d_in[14];
    const float* w1  = (const float*)d_in[15];
    const float* b1  = (const float*)d_in[16];
    const float* g1  = (const float*)d_in[17];
    const float* be1 = (const float*)d_in[18];
    const float* w2  = (const float*)d_in[19];
    const float* b2  = (const float*)d_in[20];
    const float* g2  = (const float*)d_in[21];
    const float* be2 = (const float*)d_in[22];
    const float* w3  = (const float*)d_in[23];
    const float* b3  = (const float*)d_in[24];
    float* out = (float*)d_out;

    cudaFuncSetAttribute(fused_mlp_kernel, cudaFuncAttributeMaxDynamicSharedMemorySize, 196608);
    cudaFuncSetAttribute(fused_fc_kernel,  cudaFuncAttributeMaxDynamicSharedMemorySize, 196608);

    fps_prep_kernel<<<148, 1024>>>(xyz, w0, wm1, wm2, w1, w2, w3);
    ballquery_kernel<<<BB, 256>>>(xyz);
    fused_mlp_kernel<<<NROWS/128, 256, 196608>>>(xyz, features,
                                                 b0, gm0, be0,
                                                 bm1, gm1, bem1,
                                                 bm2, gm2, bem2);
    fused_fc_kernel<<<NG/128, 256, 196608>>>(b1, g1, be1, b2, g2, be2, b3, msz, out);
    tail_kernel<<<(NG*3 + 255)/256, 256>>>(out);
}